// round 16
// baseline (speedup 1.0000x reference)
#include <cuda_runtime.h>
#include <math.h>
#include <stdint.h>

typedef unsigned long long ull;
typedef unsigned short u16;

#define NN 4096
#define UN 256
#define BT 512

// ================= helpers =================
__device__ __forceinline__ uint32_t smem_u32(const void* p){
    uint32_t a;
    asm("{ .reg .u64 t; cvta.to.shared.u64 t, %1; cvt.u32.u64 %0, t; }" : "=r"(a) : "l"(p));
    return a;
}
__device__ __forceinline__ void cpasync16(uint32_t daddr, const void* gptr){
    asm volatile("cp.async.cg.shared.global [%0], [%1], 16;" :: "r"(daddr), "l"(gptr));
}
#define CP_COMMIT asm volatile("cp.async.commit_group;" ::: "memory")
#define CP_WAIT0  asm volatile("cp.async.wait_group 0;" ::: "memory")

// fp16 hi/lo split helpers
__device__ __forceinline__ void split2h(float v0, float v1, uint32_t& hp, uint32_t& lp){
    u16 h0, h1, l0, l1;
    asm("cvt.rn.f16.f32 %0, %1;" : "=h"(h0) : "f"(v0));
    asm("cvt.rn.f16.f32 %0, %1;" : "=h"(h1) : "f"(v1));
    float f0, f1;
    asm("cvt.f32.f16 %0, %1;" : "=f"(f0) : "h"(h0));
    asm("cvt.f32.f16 %0, %1;" : "=f"(f1) : "h"(h1));
    asm("cvt.rn.f16.f32 %0, %1;" : "=h"(l0) : "f"(v0 - f0));
    asm("cvt.rn.f16.f32 %0, %1;" : "=h"(l1) : "f"(v1 - f1));
    asm("mov.b32 %0, {%1, %2};" : "=r"(hp) : "h"(h0), "h"(h1));
    asm("mov.b32 %0, {%1, %2};" : "=r"(lp) : "h"(l0), "h"(l1));
}
__device__ __forceinline__ void split1h(float v, u16& h, u16& l){
    u16 hb, lb;
    asm("cvt.rn.f16.f32 %0, %1;" : "=h"(hb) : "f"(v));
    float hf;
    asm("cvt.f32.f16 %0, %1;" : "=f"(hf) : "h"(hb));
    asm("cvt.rn.f16.f32 %0, %1;" : "=h"(lb) : "f"(v - hf));
    h = hb; l = lb;
}
__device__ __forceinline__ u16 cvt1h(float v){
    u16 hb;
    asm("cvt.rn.f16.f32 %0, %1;" : "=h"(hb) : "f"(v));
    return hb;
}

__device__ __forceinline__ void mma16816h(float* d, const uint32_t* a, const uint32_t* b){
    asm volatile("mma.sync.aligned.m16n8k16.row.col.f32.f16.f16.f32 "
        "{%0,%1,%2,%3}, {%4,%5,%6,%7}, {%8,%9}, {%0,%1,%2,%3};"
        : "+f"(d[0]), "+f"(d[1]), "+f"(d[2]), "+f"(d[3])
        : "r"(a[0]), "r"(a[1]), "r"(a[2]), "r"(a[3]), "r"(b[0]), "r"(b[1]));
}

// ================= static device scratch =================
__device__ __align__(16) float g_partialG[2u * NN * UN];   // 8 MB
__device__ __align__(16) u16   g_wth[UN * NN];             // 2 MB  w_gcn^T fp16
__device__ __align__(16) u16   g_Gt_hi[UN * NN];           // 2 MB
__device__ __align__(16) u16   g_Gt_lo[UN * NN];           // 2 MB
__device__ __align__(16) float g_partialX[8u * BT * UN];   // 4 MB
__device__ __align__(16) u16   g_gw_hi[512 * 512];         // 512 KB
__device__ __align__(16) u16   g_gw_lo[512 * 512];         // 512 KB

// ================= SMEM geometry =================
// kernelA: BK=64, ROWB=144 (128B data + 16 pad): [A_hi 18432][A_lo 18432][B 18432]
#define A_ROWB    144
#define A_OFF_AHI 0
#define A_OFF_ALO 18432
#define A_OFF_B   36864
#define A_BUFST   55296
#define A_SMEMSZ  (2 * A_BUFST)     // 110592
// kernelB: BK=32, ROWB=80
#define ROWB 80
#define B_OFF_AHI 0
#define B_OFF_ALO 5120
#define B_OFF_BHI 10240
#define B_OFF_BLO 20480
#define B_BUFST   30720
#define B_SMEMSZ  (2 * B_BUFST)
// kernelC
#define C_OFF_AHI 0
#define C_OFF_ALO 2560
#define C_OFF_BHI 5120
#define C_OFF_BLO 15360
#define C_BUFST   25600
#define C_SMEMSZ  (2 * C_BUFST)

// =====================================================================
// kPrepAll: blocks [0,1024): w_gcn transpose->fp16; [1024,1280): gate weights
// =====================================================================
__global__ void kPrepAll(const float* __restrict__ wgcn,
                         const float* __restrict__ wz, const float* __restrict__ uz,
                         const float* __restrict__ wh, const float* __restrict__ uh)
{
    __shared__ float tile[32][33];
    const int c = threadIdx.x & 31, r = threadIdx.x >> 5;
    int bx = blockIdx.x;
    if (bx < 1024){
        const int k0 = (bx & 127) * 32, n0 = (bx >> 7) * 32;
#pragma unroll
        for (int i = 0; i < 4; i++)
            tile[r + 8*i][c] = wgcn[(size_t)(k0 + r + 8*i) * UN + n0 + c];
        __syncthreads();
#pragma unroll
        for (int i = 0; i < 4; i++){
            size_t o = (size_t)(n0 + r + 8*i) * NN + k0 + c;
            g_wth[o] = cvt1h(tile[c][r + 8*i]);
        }
    } else {
        bx -= 1024;
        const int k0 = (bx & 15) * 32, n0 = (bx >> 4) * 32;
#pragma unroll
        for (int i = 0; i < 4; i++){
            int kk = k0 + r + 8*i;
            int nn = n0 + c;
            const float* src = (kk < 256) ? ((nn < 256) ? wz : wh) : ((nn < 256) ? uz : uh);
            tile[r + 8*i][c] = src[(size_t)(kk & 255) * UN + (nn & 255)];
        }
        __syncthreads();
#pragma unroll
        for (int i = 0; i < 4; i++){
            float v = tile[c][r + 8*i];
            size_t o = (size_t)(n0 + r + 8*i) * 512 + k0 + c;
            split1h(v, g_gw_hi[o], g_gw_lo[o]);
        }
    }
}

// =====================================================================
// kernelA: partialG[ks] = adj_mix[m0:m0+128, ks*2048:+2048] @ w_gcn
// fp16 2-term; grid (32 m, 2 n, 2 ksplit) = 128 CTAs, BK=64, 32 stages.
// MMA issue reordered term-major (same-acc distance 4).
// =====================================================================
#define KA_NST 32     // 2048 / 64

__global__ __launch_bounds__(256, 1) void kernelA(const float* __restrict__ adj,
                                                  const float* __restrict__ wap)
{
    extern __shared__ __align__(16) char smem[];
    const uint32_t sb = smem_u32(smem);
    const int tid = threadIdx.x, wid = tid >> 5, lane = tid & 31;
    const int g = lane >> 2, tig = lane & 3;
    const int m0 = blockIdx.x * 128, n0 = blockIdx.y * 128;
    const int kbase = blockIdx.z * 2048;
    const float w0 = wap[0], w1 = wap[1], w2 = wap[2];
    const size_t GS = (size_t)NN * NN;

    float acc[4][4][4];
#pragma unroll
    for (int a = 0; a < 4; a++)
#pragma unroll
        for (int b = 0; b < 4; b++)
#pragma unroll
            for (int c = 0; c < 4; c++) acc[a][b][c] = 0.f;

    float4 ra[4][3];

    auto issueB = [&](int t, int b){
#pragma unroll
        for (int j = 0; j < 4; j++){
            int f = j*256 + tid, row = f >> 3, c = f & 7;
            uint32_t daddr = sb + b*A_BUFST + A_OFF_B + row*A_ROWB + c*16;
            size_t go = (size_t)(n0 + row) * NN + kbase + t*64 + c*8;
            cpasync16(daddr, g_wth + go);
        }
        CP_COMMIT;
    };
    auto loadA = [&](int t, int h){
#pragma unroll
        for (int j = 0; j < 4; j++){
            int f = j*256 + tid, row = f >> 3, q = f & 7;
            const float* p = adj + (size_t)(m0 + row) * NN + kbase + t*64 + h*32 + q*4;
            ra[j][0] = __ldg((const float4*)p);
            ra[j][1] = __ldg((const float4*)(p + GS));
            ra[j][2] = __ldg((const float4*)(p + 2*GS));
        }
    };
    auto storeA = [&](int b, int h){
        char* base = smem + b*A_BUFST;
#pragma unroll
        for (int j = 0; j < 4; j++){
            int f = j*256 + tid, row = f >> 3, q = f & 7;
            float vx = fmaf(w0, ra[j][0].x, fmaf(w1, ra[j][1].x, w2*ra[j][2].x));
            float vy = fmaf(w0, ra[j][0].y, fmaf(w1, ra[j][1].y, w2*ra[j][2].y));
            float vz = fmaf(w0, ra[j][0].z, fmaf(w1, ra[j][1].z, w2*ra[j][2].z));
            float vw = fmaf(w0, ra[j][0].w, fmaf(w1, ra[j][1].w, w2*ra[j][2].w));
            uint32_t h0, l0, h1, l1;
            split2h(vx, vy, h0, l0);
            split2h(vz, vw, h1, l1);
            int off = row*A_ROWB + h*64 + q*8;
            *(uint2*)(base + A_OFF_AHI + off) = make_uint2(h0, h1);
            *(uint2*)(base + A_OFF_ALO + off) = make_uint2(l0, l1);
        }
    };

    const int am = (wid & 1) * 64 + g;
    const int bn = (wid >> 1) * 32 + g;

    auto mma_half = [&](const char* buf, int s0){
#pragma unroll
        for (int s = s0; s < s0 + 2; s++){
            const int ko = s * 32 + tig * 4;
            uint32_t bh[4][2];
#pragma unroll
            for (int ni = 0; ni < 4; ni++){
                const char* p = buf + A_OFF_B + (bn + ni*8) * A_ROWB + ko;
                bh[ni][0] = *(const uint32_t*)p;
                bh[ni][1] = *(const uint32_t*)(p + 16);
            }
#pragma unroll
            for (int mi = 0; mi < 4; mi++){
                const char* p = buf + A_OFF_AHI + (am + mi*16) * A_ROWB + ko;
                uint32_t ah[4] = { *(const uint32_t*)p,        *(const uint32_t*)(p + 8*A_ROWB),
                                   *(const uint32_t*)(p + 16), *(const uint32_t*)(p + 8*A_ROWB + 16) };
                const char* q = buf + A_OFF_ALO + (am + mi*16) * A_ROWB + ko;
                uint32_t al[4] = { *(const uint32_t*)q,        *(const uint32_t*)(q + 8*A_ROWB),
                                   *(const uint32_t*)(q + 16), *(const uint32_t*)(q + 8*A_ROWB + 16) };
                // term-major: all hi MMAs, then all lo MMAs (same-acc distance 4)
#pragma unroll
                for (int ni = 0; ni < 4; ni++)
                    mma16816h(acc[mi][ni], ah, bh[ni]);
#pragma unroll
                for (int ni = 0; ni < 4; ni++)
                    mma16816h(acc[mi][ni], al, bh[ni]);
            }
        }
    };

    issueB(0, 0);
    loadA(0, 0); storeA(0, 0);
    loadA(0, 1); storeA(0, 1);
    CP_WAIT0; __syncthreads();

    for (int t = 0; t < KA_NST; t++){
        const int b = t & 1;
        const char* buf = smem + b*A_BUFST;
        if (t + 1 < KA_NST){
            issueB(t + 1, b ^ 1);
            loadA(t + 1, 0);
            mma_half(buf, 0);
            storeA(b ^ 1, 0);
            loadA(t + 1, 1);
            mma_half(buf, 2);
            storeA(b ^ 1, 1);
        } else {
            mma_half(buf, 0);
            mma_half(buf, 2);
        }
        CP_WAIT0; __syncthreads();
    }

    float* dst = g_partialG + (size_t)blockIdx.z * (NN * UN);
#pragma unroll
    for (int mi = 0; mi < 4; mi++){
#pragma unroll
        for (int ni = 0; ni < 4; ni++){
            int m = m0 + (wid & 1)*64 + mi*16 + g;
            int n = n0 + (wid >> 1)*32 + ni*8 + tig*2;
            *(float2*)(dst + (size_t)m * UN + n)       = make_float2(acc[mi][ni][0], acc[mi][ni][1]);
            *(float2*)(dst + (size_t)(m + 8) * UN + n) = make_float2(acc[mi][ni][2], acc[mi][ni][3]);
        }
    }
}

// =====================================================================
// kReduceGT: G = sum of 2 partials; transpose + fp16 split (vectorized)
// =====================================================================
__global__ void kReduceGT()
{
    __shared__ float tile[32][33];
    const int k0 = blockIdx.x * 32, n0 = blockIdx.y * 32;
    const int tid = threadIdx.x;
    {
        const int r = tid >> 3, q = tid & 7;
        size_t o = (size_t)(k0 + r) * UN + n0 + q*4;
        float4 a = *(const float4*)(g_partialG + o);
        float4 b = *(const float4*)(g_partialG + (size_t)NN*UN + o);
        tile[r][q*4+0] = a.x + b.x;
        tile[r][q*4+1] = a.y + b.y;
        tile[r][q*4+2] = a.z + b.z;
        tile[r][q*4+3] = a.w + b.w;
    }
    __syncthreads();
    {
        const int nr = tid >> 3, kq = tid & 7;
        u16 hh[4], ll[4];
#pragma unroll
        for (int j = 0; j < 4; j++)
            split1h(tile[kq*4+j][nr], hh[j], ll[j]);
        size_t o = (size_t)(n0 + nr) * NN + k0 + kq*4;
        *(uint2*)(g_Gt_hi + o) = *(uint2*)hh;
        *(uint2*)(g_Gt_lo + o) = *(uint2*)ll;
    }
}

// =====================================================================
// kernelB: partialX[ks] = inputs @ G  (fp16 3-term)
// grid (8 m, 2 n, 8 ksplit) = 128 CTAs. MMA issue term-major (distance 8).
// =====================================================================
#define KB_NST 16

__global__ __launch_bounds__(256, 2) void kernelB(const float* __restrict__ inputs)
{
    extern __shared__ __align__(16) char smem[];
    const uint32_t sb = smem_u32(smem);
    const int tid = threadIdx.x, wid = tid >> 5, lane = tid & 31;
    const int g = lane >> 2, tig = lane & 3;
    const int m0 = blockIdx.x * 64, n0 = blockIdx.y * 128;
    const int kbase = blockIdx.z * 512;

    float acc[2][4][4];
#pragma unroll
    for (int a = 0; a < 2; a++)
#pragma unroll
        for (int b = 0; b < 4; b++)
#pragma unroll
            for (int c = 0; c < 4; c++) acc[a][b][c] = 0.f;

    float4 ra[2];

    auto issueB = [&](int t, int b){
#pragma unroll
        for (int j = 0; j < 2; j++){
            int f = j*256 + tid, row = f >> 2, c = f & 3;
            uint32_t daddr = sb + b*B_BUFST + row*ROWB + c*16;
            size_t go = (size_t)(n0 + row) * NN + kbase + t*32 + c*8;
            cpasync16(daddr + B_OFF_BHI, g_Gt_hi + go);
            cpasync16(daddr + B_OFF_BLO, g_Gt_lo + go);
        }
        CP_COMMIT;
    };
    auto loadA = [&](int t){
#pragma unroll
        for (int j = 0; j < 2; j++){
            int f = j*256 + tid, row = f >> 3, q = f & 7;
            ra[j] = __ldg((const float4*)(inputs + (size_t)(m0 + row) * NN + kbase + t*32 + q*4));
        }
    };
    auto storeA = [&](int b){
        char* base = smem + b*B_BUFST;
#pragma unroll
        for (int j = 0; j < 2; j++){
            int f = j*256 + tid, row = f >> 3, q = f & 7;
            uint32_t h0, l0, h1, l1;
            split2h(ra[j].x, ra[j].y, h0, l0);
            split2h(ra[j].z, ra[j].w, h1, l1);
            *(uint2*)(base + B_OFF_AHI + row*ROWB + q*8) = make_uint2(h0, h1);
            *(uint2*)(base + B_OFF_ALO + row*ROWB + q*8) = make_uint2(l0, l1);
        }
    };

    issueB(0, 0);
    loadA(0); storeA(0);
    CP_WAIT0; __syncthreads();

    const int am = (wid & 1) * 32 + g;
    const int bn = (wid >> 1) * 32 + g;

    for (int t = 0; t < KB_NST; t++){
        const int b = t & 1;
        if (t + 1 < KB_NST){ issueB(t + 1, b ^ 1); loadA(t + 1); }

        const char* buf = smem + b*B_BUFST;
#pragma unroll
        for (int s = 0; s < 2; s++){
            const int ko = s * 32 + tig * 4;
            uint32_t ah[2][4], al[2][4];
#pragma unroll
            for (int mi = 0; mi < 2; mi++){
                const char* pa = buf + B_OFF_AHI + (am + mi*16) * ROWB + ko;
                ah[mi][0] = *(const uint32_t*)pa;        ah[mi][1] = *(const uint32_t*)(pa + 8*ROWB);
                ah[mi][2] = *(const uint32_t*)(pa + 16); ah[mi][3] = *(const uint32_t*)(pa + 8*ROWB + 16);
                const char* ql = buf + B_OFF_ALO + (am + mi*16) * ROWB + ko;
                al[mi][0] = *(const uint32_t*)ql;        al[mi][1] = *(const uint32_t*)(ql + 8*ROWB);
                al[mi][2] = *(const uint32_t*)(ql + 16); al[mi][3] = *(const uint32_t*)(ql + 8*ROWB + 16);
            }
            uint32_t bh[4][2], bl[4][2];
#pragma unroll
            for (int ni = 0; ni < 4; ni++){
                const char* pb = buf + B_OFF_BHI + (bn + ni*8) * ROWB + ko;
                bh[ni][0] = *(const uint32_t*)pb;
                bh[ni][1] = *(const uint32_t*)(pb + 16);
                const char* qb = buf + B_OFF_BLO + (bn + ni*8) * ROWB + ko;
                bl[ni][0] = *(const uint32_t*)qb;
                bl[ni][1] = *(const uint32_t*)(qb + 16);
            }
            // term-major sweeps (same-acc distance 8)
#pragma unroll
            for (int ni = 0; ni < 4; ni++)
#pragma unroll
                for (int mi = 0; mi < 2; mi++)
                    mma16816h(acc[mi][ni], ah[mi], bh[ni]);
#pragma unroll
            for (int ni = 0; ni < 4; ni++)
#pragma unroll
                for (int mi = 0; mi < 2; mi++)
                    mma16816h(acc[mi][ni], ah[mi], bl[ni]);
#pragma unroll
            for (int ni = 0; ni < 4; ni++)
#pragma unroll
                for (int mi = 0; mi < 2; mi++)
                    mma16816h(acc[mi][ni], al[mi], bh[ni]);
        }

        if (t + 1 < KB_NST) storeA(b ^ 1);
        CP_WAIT0; __syncthreads();
    }

    float* dst = g_partialX + (size_t)blockIdx.z * (BT * UN);
#pragma unroll
    for (int mi = 0; mi < 2; mi++){
        int m = m0 + am + mi*16;
#pragma unroll
        for (int ni = 0; ni < 4; ni++){
            int n = n0 + bn - g + ni*8 + tig*2;
            *(float2*)(dst + (size_t)m * UN + n)       = make_float2(acc[mi][ni][0], acc[mi][ni][1]);
            *(float2*)(dst + (size_t)(m + 8) * UN + n) = make_float2(acc[mi][ni][2], acc[mi][ni][3]);
        }
    }
}

// =====================================================================
// kernelC: fused GRU gate GEMM + epilogue; reduceX+relu folded into loadA.
// grid (16 m, 4 n) = 64 CTAs. MMA issue term-major (distance 4).
// =====================================================================
#define KC_NST 16

__global__ __launch_bounds__(256, 2) void kernelC(const float* __restrict__ state,
    const float* __restrict__ bz, const float* __restrict__ bh,
    float* __restrict__ out)
{
    extern __shared__ __align__(16) char smem[];
    const uint32_t sb = smem_u32(smem);
    const int tid = threadIdx.x, wid = tid >> 5, lane = tid & 31;
    const int g = lane >> 2, tig = lane & 3;
    const int m0 = blockIdx.x * 32;
    const int n0 = blockIdx.y * 64;

    float accz[2][4], acch[2][4];
#pragma unroll
    for (int a = 0; a < 2; a++)
#pragma unroll
        for (int c = 0; c < 4; c++){ accz[a][c] = 0.f; acch[a][c] = 0.f; }

    const int arow = tid >> 3;
    const int aq   = tid & 7;
    float4 ra;

    auto issueB = [&](int t, int b){
#pragma unroll
        for (int j = 0; j < 2; j++){
            int f = j*256 + tid, r = f >> 2, c = f & 3;
            int nprime = (r < 64) ? (n0 + r) : (256 + n0 + (r - 64));
            uint32_t daddr = sb + b*C_BUFST + r*ROWB + c*16;
            size_t go = (size_t)nprime * 512 + t*32 + c*8;
            cpasync16(daddr + C_OFF_BHI, g_gw_hi + go);
            cpasync16(daddr + C_OFF_BLO, g_gw_lo + go);
        }
        CP_COMMIT;
    };
    auto loadA = [&](int t){
        int kp = t*32 + aq*4;
        if (kp < 256){
            size_t o = (size_t)(m0 + arow) * UN + kp;
            float4 s = *(const float4*)(g_partialX + o);
#pragma unroll
            for (int pl = 1; pl < 8; pl++){
                float4 t4 = __ldg((const float4*)(g_partialX + (size_t)pl * (BT*UN) + o));
                s.x += t4.x; s.y += t4.y; s.z += t4.z; s.w += t4.w;
            }
            ra.x = fmaxf(s.x, 0.f); ra.y = fmaxf(s.y, 0.f);
            ra.z = fmaxf(s.z, 0.f); ra.w = fmaxf(s.w, 0.f);
        } else {
            ra = __ldg((const float4*)(state + (size_t)(m0 + arow) * UN + (kp - 256)));
        }
    };
    auto storeA = [&](int b){
        char* base = smem + b*C_BUFST;
        uint32_t h0, l0, h1, l1;
        split2h(ra.x, ra.y, h0, l0);
        split2h(ra.z, ra.w, h1, l1);
        *(uint2*)(base + C_OFF_AHI + arow*ROWB + aq*8) = make_uint2(h0, h1);
        *(uint2*)(base + C_OFF_ALO + arow*ROWB + aq*8) = make_uint2(l0, l1);
    };

    issueB(0, 0);
    loadA(0); storeA(0);
    CP_WAIT0; __syncthreads();

    const int am = (wid & 1) * 16 + g;
    const int bn = (wid >> 1) * 16;

    for (int t = 0; t < KC_NST; t++){
        const int b = t & 1;
        if (t + 1 < KC_NST){ issueB(t + 1, b ^ 1); loadA(t + 1); }

        const char* buf = smem + b*C_BUFST;
#pragma unroll
        for (int s = 0; s < 2; s++){
            const int ko = s * 32 + tig * 4;
            const char* pa = buf + C_OFF_AHI + am * ROWB + ko;
            uint32_t ah[4] = { *(const uint32_t*)pa,        *(const uint32_t*)(pa + 8*ROWB),
                               *(const uint32_t*)(pa + 16), *(const uint32_t*)(pa + 8*ROWB + 16) };
            const char* ql = buf + C_OFF_ALO + am * ROWB + ko;
            uint32_t al[4] = { *(const uint32_t*)ql,        *(const uint32_t*)(ql + 8*ROWB),
                               *(const uint32_t*)(ql + 16), *(const uint32_t*)(ql + 8*ROWB + 16) };
            uint32_t bhz[2][2], blz[2][2], bhh[2][2], blh[2][2];
#pragma unroll
            for (int ni = 0; ni < 2; ni++){
                const char* pb = buf + C_OFF_BHI + (bn + g + ni*8) * ROWB + ko;
                bhz[ni][0] = *(const uint32_t*)pb;  bhz[ni][1] = *(const uint32_t*)(pb + 16);
                const char* qb = buf + C_OFF_BLO + (bn + g + ni*8) * ROWB + ko;
                blz[ni][0] = *(const uint32_t*)qb;  blz[ni][1] = *(const uint32_t*)(qb + 16);
                const char* ph = buf + C_OFF_BHI + (64 + bn + g + ni*8) * ROWB + ko;
                bhh[ni][0] = *(const uint32_t*)ph;  bhh[ni][1] = *(const uint32_t*)(ph + 16);
                const char* qh = buf + C_OFF_BLO + (64 + bn + g + ni*8) * ROWB + ko;
                blh[ni][0] = *(const uint32_t*)qh;  blh[ni][1] = *(const uint32_t*)(qh + 16);
            }
            // term-major across 4 accumulators (distance 4)
#pragma unroll
            for (int ni = 0; ni < 2; ni++) mma16816h(accz[ni], ah, bhz[ni]);
#pragma unroll
            for (int ni = 0; ni < 2; ni++) mma16816h(acch[ni], ah, bhh[ni]);
#pragma unroll
            for (int ni = 0; ni < 2; ni++) mma16816h(accz[ni], ah, blz[ni]);
#pragma unroll
            for (int ni = 0; ni < 2; ni++) mma16816h(acch[ni], ah, blh[ni]);
#pragma unroll
            for (int ni = 0; ni < 2; ni++) mma16816h(accz[ni], al, bhz[ni]);
#pragma unroll
            for (int ni = 0; ni < 2; ni++) mma16816h(acch[ni], al, bhh[ni]);
        }

        if (t + 1 < KC_NST) storeA(b ^ 1);
        CP_WAIT0; __syncthreads();
    }

#pragma unroll
    for (int ni = 0; ni < 2; ni++){
        int n = n0 + bn + ni*8 + tig*2;
        float2 bzv = *(const float2*)(bz + n);
        float2 bhv = *(const float2*)(bh + n);
#pragma unroll
        for (int half = 0; half < 2; half++){
            int m = m0 + am + half*8;
            float pz0 = accz[ni][half*2+0] + bzv.x;
            float pz1 = accz[ni][half*2+1] + bzv.y;
            float ph0 = acch[ni][half*2+0] + bhv.x;
            float ph1 = acch[ni][half*2+1] + bhv.y;
            float2 sv = *(const float2*)(state + (size_t)m * UN + n);
            float z0 = 1.0f / (1.0f + expf(-pz0));
            float z1 = 1.0f / (1.0f + expf(-pz1));
            float h0 = tanhf(ph0);
            float h1 = tanhf(ph1);
            float o0 = sv.x + z0 * (h0 - sv.x);
            float o1 = sv.y + z1 * (h1 - sv.y);
            *(float2*)(out + (size_t)m * UN + n) = make_float2(o0, o1);
        }
    }
}

// =====================================================================
extern "C" void kernel_launch(void* const* d_in, const int* in_sizes, int n_in,
                              void* d_out, int out_size)
{
    const float* inputs = (const float*)d_in[0];
    const float* state  = (const float*)d_in[1];
    const float* adj    = (const float*)d_in[2];
    const float* wa     = (const float*)d_in[3];
    const float* wgcn   = (const float*)d_in[4];
    const float* wz     = (const float*)d_in[5];
    const float* uz     = (const float*)d_in[6];
    const float* bz     = (const float*)d_in[7];
    const float* wh     = (const float*)d_in[8];
    const float* uh     = (const float*)d_in[9];
    const float* bh     = (const float*)d_in[10];
    float* out = (float*)d_out;

    cudaFuncSetAttribute(kernelA, cudaFuncAttributeMaxDynamicSharedMemorySize, A_SMEMSZ);
    cudaFuncSetAttribute(kernelB, cudaFuncAttributeMaxDynamicSharedMemorySize, B_SMEMSZ);
    cudaFuncSetAttribute(kernelC, cudaFuncAttributeMaxDynamicSharedMemorySize, C_SMEMSZ);

    kPrepAll<<<1280, 256>>>(wgcn, wz, uz, wh, uh);
    kernelA<<<dim3(32, 2, 2), 256, A_SMEMSZ>>>(adj, wa);
    kReduceGT<<<dim3(NN/32, UN/32), 256>>>();
    kernelB<<<dim3(8, 2, 8), 256, B_SMEMSZ>>>(inputs);
    kernelC<<<dim3(16, 4), 256, C_SMEMSZ>>>(state, bz, bh, out);
}